// round 1
// baseline (speedup 1.0000x reference)
#include <cuda_runtime.h>
#include <cuda_bf16.h>
#include <cstdint>

// Problem constants
#define BB 8
#define NN 50000
#define CC 8
#define CAP 2048
#define KP 1024
#define MAXD 100
#define SCORE_THR 0.99f
#define NMS_THR 0.5f
#define NEGV (-1e30f)

typedef unsigned long long u64;
typedef unsigned int u32;

// Scratch (device globals; no allocations allowed)
__device__ int   g_cnt[BB * CC];
__device__ float g_cscore[BB * CC * CAP];
__device__ int   g_cidx[BB * CC * CAP];
__device__ float g_keep_score[BB * CC * KP];
__device__ int   g_keep_idx[BB * CC * KP];

// ---------------------------------------------------------------------------
__global__ void k0_init() {
    int t = threadIdx.x;
    if (t < BB * CC) g_cnt[t] = 0;
}

// ---------------------------------------------------------------------------
// Candidate compaction: one thread per (b,n), reads 8 class scores (32B).
__global__ void k1_cand(const float* __restrict__ cls) {
    int t = blockIdx.x * blockDim.x + threadIdx.x;
    if (t >= BB * NN) return;
    int b = t / NN;
    int n = t - b * NN;
    const float4* p = reinterpret_cast<const float4*>(cls + (size_t)t * CC);
    float4 v0 = p[0], v1 = p[1];
    float v[8] = {v0.x, v0.y, v0.z, v0.w, v1.x, v1.y, v1.z, v1.w};
#pragma unroll
    for (int c = 0; c < 8; c++) {
        if (v[c] > SCORE_THR) {
            int pos = atomicAdd(&g_cnt[b * CC + c], 1);
            if (pos < CAP) {
                g_cscore[(b * CC + c) * CAP + pos] = v[c];
                g_cidx[(b * CC + c) * CAP + pos]   = n;
            }
        }
    }
}

// ---------------------------------------------------------------------------
// Bitonic sort, descending, n power of 2, nthreads threads cooperating.
__device__ __forceinline__ void bitonic_desc(u64* s, int n, int tid, int nthreads) {
    for (int k = 2; k <= n; k <<= 1) {
        for (int j = k >> 1; j > 0; j >>= 1) {
            for (int i = tid; i < n; i += nthreads) {
                int ixj = i ^ j;
                if (ixj > i) {
                    u64 a = s[i], c = s[ixj];
                    bool up = ((i & k) == 0);  // descending segment
                    if (up ? (a < c) : (a > c)) { s[i] = c; s[ixj] = a; }
                }
            }
            __syncthreads();
        }
    }
}

// ---------------------------------------------------------------------------
// Per-(b,c): sort candidates (stable tie-break by lower original index),
// greedy NMS via bit-matrix + single-warp sequential scan.
// Dynamic smem layout:
//   [0      ,  16384) u64  keys[2048]
//   [16384  ,  36864) float bx1/by1/bx2/by2/area [1024 each]
//   [36864  , 167936) u32  mask[1024*32]
//   [167936 , 168064) u32  keepw[32]
#define K2_SMEM 168064

__global__ void k2_nms(const float* __restrict__ boxes) {
    extern __shared__ unsigned char smem[];
    u64*   keys = reinterpret_cast<u64*>(smem);
    float* bx1  = reinterpret_cast<float*>(smem + 16384);
    float* by1  = bx1 + 1024;
    float* bx2  = by1 + 1024;
    float* by2  = bx2 + 1024;
    float* ar   = by2 + 1024;
    u32*   mask = reinterpret_cast<u32*>(smem + 36864);
    u32*   keepw = reinterpret_cast<u32*>(smem + 167936);

    int bc  = blockIdx.x;
    int b   = bc >> 3;
    int tid = threadIdx.x;

    int cnt = g_cnt[bc];
    if (cnt > CAP) cnt = CAP;

    // Load packed keys: score bits << 32 | ~idx (tie-break: smaller idx first)
    for (int t = tid; t < CAP; t += 1024) {
        u64 k = 0ull;
        if (t < cnt) {
            u32 sb = __float_as_uint(g_cscore[bc * CAP + t]);
            u32 iv = ~(u32)g_cidx[bc * CAP + t];
            k = ((u64)sb << 32) | (u64)iv;
        }
        keys[t] = k;
    }
    __syncthreads();
    bitonic_desc(keys, CAP, tid, 1024);

    int M = cnt < KP ? cnt : KP;

    // Gather candidate boxes into smem
    if (tid < M) {
        int idx = (int)(~(u32)keys[tid]);
        const float* bp = boxes + ((size_t)(b * NN + idx)) * 4;
        float x1 = bp[0], y1 = bp[1], x2 = bp[2], y2 = bp[3];
        bx1[tid] = x1; by1[tid] = y1; bx2[tid] = x2; by2[tid] = y2;
        ar[tid] = __fmul_rn(__fsub_rn(x2, x1), __fsub_rn(y2, y1));
    }
    __syncthreads();

    // Build suppression bit matrix: mask[i][w] bit l set iff
    // j = w*32+l, j > i, j < M, IoU(i,j) > NMS_THR.
    int warp = tid >> 5, lane = tid & 31;
    for (int task = warp; task < M * 32; task += 32) {
        int i  = task >> 5;
        int jw = task & 31;
        int j  = (jw << 5) + lane;
        bool p = false;
        if (j > i && j < M) {
            float iw = fmaxf(__fsub_rn(fminf(bx2[i], bx2[j]), fmaxf(bx1[i], bx1[j])), 0.0f);
            float ih = fmaxf(__fsub_rn(fminf(by2[i], by2[j]), fmaxf(by1[i], by1[j])), 0.0f);
            float inter = __fmul_rn(iw, ih);
            float denom = __fsub_rn(__fadd_rn(ar[i], ar[j]), inter);
            p = __fdiv_rn(inter, denom) > NMS_THR;
        }
        u32 w = __ballot_sync(0xffffffffu, p);
        if (lane == 0) mask[(i << 5) + jw] = w;
    }
    __syncthreads();

    // Sequential greedy scan: warp 0 only. remv distributed across 32 lanes.
    if (warp == 0) {
        u32 remv = 0u, kw = 0u;
        for (int i = 0; i < M; i++) {
            u32 r = __shfl_sync(0xffffffffu, remv, i >> 5);
            if (!((r >> (i & 31)) & 1u)) {
                if (lane == (i >> 5)) kw |= (1u << (i & 31));
                remv |= mask[(i << 5) + lane];
            }
        }
        keepw[lane] = kw;
    }
    __syncthreads();

    // Emit per-(b,c) keep lists
    {
        int t = tid;
        float s = NEGV;
        int idx = 0;
        if (t < M) {
            u64 k = keys[t];
            idx = (int)(~(u32)k);
            bool kp = (keepw[t >> 5] >> (t & 31)) & 1u;
            if (kp) s = __uint_as_float((u32)(k >> 32));
        }
        g_keep_score[bc * KP + t] = s;
        g_keep_idx[bc * KP + t]   = idx;
    }
}

// ---------------------------------------------------------------------------
// Per-batch final top-100 + output assembly.
// Output layout (float32): boxes[8,100,4] | scores[8,100] | labels[8,100] |
//                          rot[8,100,3]   | trans[8,100,3]   => 9600 floats
#define K3_SMEM (8192 * 8)

__global__ void k3_topk(const float* __restrict__ boxes,
                        const float* __restrict__ rot,
                        const float* __restrict__ trans,
                        float* __restrict__ out) {
    extern __shared__ unsigned char smem[];
    u64* keys = reinterpret_cast<u64*>(smem);
    int b = blockIdx.x, tid = threadIdx.x;

    for (int t = tid; t < CC * KP; t += 1024) {
        float s = g_keep_score[b * CC * KP + t];
        u64 k = 0ull;
        if (s > SCORE_THR) {
            // tie-break: smaller flattened position (c*KP + slot) first
            k = ((u64)__float_as_uint(s) << 32) | (u64)(~(u32)t);
        }
        keys[t] = k;
    }
    __syncthreads();
    bitonic_desc(keys, CC * KP, tid, 1024);

    if (tid < MAXD) {
        float* ob   = out;                 // 3200
        float* os   = out + 3200;          // 800
        float* ol   = out + 4000;          // 800
        float* orot = out + 4800;          // 2400
        float* otr  = out + 7200;          // 2400
        int base = b * MAXD + tid;

        u64 k = keys[tid];
        if (k != 0ull) {
            u32 meta = ~(u32)k;
            int c   = (int)(meta >> 10);
            int idx = g_keep_idx[b * CC * KP + (int)meta];
            float s = __uint_as_float((u32)(k >> 32));
            size_t g = (size_t)(b * NN + idx);
            const float* bp = boxes + g * 4;
            ob[base * 4 + 0] = bp[0];
            ob[base * 4 + 1] = bp[1];
            ob[base * 4 + 2] = bp[2];
            ob[base * 4 + 3] = bp[3];
            os[base] = s;
            ol[base] = (float)c;
            const float* rp = rot + g * 3;
            orot[base * 3 + 0] = rp[0];
            orot[base * 3 + 1] = rp[1];
            orot[base * 3 + 2] = rp[2];
            const float* tp = trans + g * 3;
            otr[base * 3 + 0] = tp[0];
            otr[base * 3 + 1] = tp[1];
            otr[base * 3 + 2] = tp[2];
        } else {
            ob[base * 4 + 0] = -1.0f;
            ob[base * 4 + 1] = -1.0f;
            ob[base * 4 + 2] = -1.0f;
            ob[base * 4 + 3] = -1.0f;
            os[base] = -1.0f;
            ol[base] = -1.0f;
            orot[base * 3 + 0] = -1.0f;
            orot[base * 3 + 1] = -1.0f;
            orot[base * 3 + 2] = -1.0f;
            otr[base * 3 + 0] = -1.0f;
            otr[base * 3 + 1] = -1.0f;
            otr[base * 3 + 2] = -1.0f;
        }
    }
}

// ---------------------------------------------------------------------------
extern "C" void kernel_launch(void* const* d_in, const int* in_sizes, int n_in,
                              void* d_out, int out_size) {
    const float* boxes = (const float*)d_in[0];
    const float* cls   = (const float*)d_in[1];
    const float* rot   = (const float*)d_in[2];
    const float* trans = (const float*)d_in[3];
    float* out = (float*)d_out;

    cudaFuncSetAttribute(k2_nms, cudaFuncAttributeMaxDynamicSharedMemorySize, K2_SMEM);
    cudaFuncSetAttribute(k3_topk, cudaFuncAttributeMaxDynamicSharedMemorySize, K3_SMEM);

    k0_init<<<1, 64>>>();
    int total = BB * NN;
    k1_cand<<<(total + 255) / 256, 256>>>(cls);
    k2_nms<<<BB * CC, 1024, K2_SMEM>>>(boxes);
    k3_topk<<<BB, 1024, K3_SMEM>>>(boxes, rot, trans, out);
}

// round 2
// speedup vs baseline: 2.7227x; 2.7227x over previous
#include <cuda_runtime.h>
#include <cuda_bf16.h>
#include <cstdint>

#define BB 8
#define NN 50000
#define CC 8
#define CAP 2048
#define KP 1024
#define MAXD 100
#define SCORE_THR 0.99f
#define NEGV (-1e30f)
#define NSPLIT 16

typedef unsigned long long u64;
typedef unsigned int u32;

// ---------------- device scratch (no allocations allowed) -------------------
__device__ int   g_cnt[BB * CC];
__device__ float g_cscore[BB * CC * CAP];
__device__ int   g_cidx[BB * CC * CAP];

__device__ int   g_M[BB * CC];
__device__ float g_sx1[BB * CC * KP];
__device__ float g_sy1[BB * CC * KP];
__device__ float g_sx2[BB * CC * KP];
__device__ float g_sy2[BB * CC * KP];
__device__ float g_sar[BB * CC * KP];
__device__ u64   g_skey[BB * CC * KP];
__device__ int   g_sidx[BB * CC * KP];

__device__ u32   g_mask[BB * CC * KP * 32];   // 8 MB, [bc][i][word]

__device__ int   g_kcnt[BB * CC];
__device__ u64   g_ckey[BB * CC * KP];        // compacted kept keys, sorted

// ---------------------------------------------------------------------------
__global__ void k0_init() {
    int t = threadIdx.x;
    if (t < BB * CC) g_cnt[t] = 0;
}

// ---------------------------------------------------------------------------
// Candidate compaction with warp-aggregated atomics.
__global__ void k1_cand(const float* __restrict__ cls) {
    int t = blockIdx.x * blockDim.x + threadIdx.x;
    bool inb = t < BB * NN;
    int b = inb ? (t / NN) : (BB - 1);
    int n = inb ? (t - b * NN) : 0;
    float v[8];
    if (inb) {
        const float4* p = reinterpret_cast<const float4*>(cls + (size_t)t * CC);
        float4 v0 = p[0], v1 = p[1];
        v[0]=v0.x; v[1]=v0.y; v[2]=v0.z; v[3]=v0.w;
        v[4]=v1.x; v[5]=v1.y; v[6]=v1.z; v[7]=v1.w;
    } else {
#pragma unroll
        for (int c = 0; c < 8; c++) v[c] = 0.0f;
    }
    int lane = threadIdx.x & 31;
    bool uniform = __shfl_sync(0xffffffffu, b, 0) == __shfl_sync(0xffffffffu, b, 31);
#pragma unroll
    for (int c = 0; c < 8; c++) {
        bool p = v[c] > SCORE_THR;
        if (uniform) {
            u32 m = __ballot_sync(0xffffffffu, p);
            if (m) {
                int leader = __ffs(m) - 1;
                int base = 0;
                if (lane == leader) base = atomicAdd(&g_cnt[b * CC + c], __popc(m));
                base = __shfl_sync(0xffffffffu, base, leader);
                if (p) {
                    int off = base + __popc(m & ((1u << lane) - 1u));
                    if (off < CAP) {
                        g_cscore[(b * CC + c) * CAP + off] = v[c];
                        g_cidx[(b * CC + c) * CAP + off]   = n;
                    }
                }
            }
        } else if (p) {
            int off = atomicAdd(&g_cnt[b * CC + c], 1);
            if (off < CAP) {
                g_cscore[(b * CC + c) * CAP + off] = v[c];
                g_cidx[(b * CC + c) * CAP + off]   = n;
            }
        }
    }
}

// ---------------------------------------------------------------------------
__device__ __forceinline__ void bitonic_desc(u64* s, int n, int tid, int nthreads) {
    for (int k = 2; k <= n; k <<= 1) {
        for (int j = k >> 1; j > 0; j >>= 1) {
            for (int i = tid; i < n; i += nthreads) {
                int ixj = i ^ j;
                if (ixj > i) {
                    u64 a = s[i], c = s[ixj];
                    bool up = ((i & k) == 0);
                    if (up ? (a < c) : (a > c)) { s[i] = c; s[ixj] = a; }
                }
            }
            __syncthreads();
        }
    }
}

// ---------------------------------------------------------------------------
// Sort candidates (size = next pow2 of cnt) + gather sorted box coords.
__global__ void k2a_sort(const float* __restrict__ boxes) {
    __shared__ u64 keys[CAP];
    int bc = blockIdx.x;
    int b  = bc >> 3;
    int tid = threadIdx.x;

    int cnt = g_cnt[bc];
    if (cnt > CAP) cnt = CAP;
    int P = 64;
    while (P < cnt) P <<= 1;

    for (int t = tid; t < P; t += 1024) {
        u64 k = 0ull;
        if (t < cnt) {
            u32 sb = __float_as_uint(g_cscore[bc * CAP + t]);
            u32 iv = ~(u32)g_cidx[bc * CAP + t];
            k = ((u64)sb << 32) | (u64)iv;
        }
        keys[t] = k;
    }
    __syncthreads();
    bitonic_desc(keys, P, tid, 1024);

    int M = cnt < KP ? cnt : KP;
    if (tid == 0) g_M[bc] = M;

    if (tid < M) {
        u64 kk = keys[tid];
        int idx = (int)(~(u32)kk);
        float4 bp = reinterpret_cast<const float4*>(boxes)[(size_t)(b * NN + idx)];
        int o = bc * KP + tid;
        g_sx1[o] = bp.x; g_sy1[o] = bp.y; g_sx2[o] = bp.z; g_sy2[o] = bp.w;
        g_sar[o] = __fmul_rn(__fsub_rn(bp.z, bp.x), __fsub_rn(bp.w, bp.y));
        g_skey[o] = kk;
        g_sidx[o] = idx;
    }
}

// ---------------------------------------------------------------------------
// Triangular IoU mask build, split across NSPLIT blocks per (b,c).
__global__ void __launch_bounds__(256) k2b_mask() {
    __shared__ float sx1[KP], sy1[KP], sx2[KP], sy2[KP], sar[KP];
    int bid = blockIdx.x;
    int bc  = bid / NSPLIT;
    int s   = bid - bc * NSPLIT;
    int M   = g_M[bc];

    for (int t = threadIdx.x; t < M; t += 256) {
        int o = bc * KP + t;
        sx1[t] = g_sx1[o]; sy1[t] = g_sy1[o];
        sx2[t] = g_sx2[o]; sy2[t] = g_sy2[o];
        sar[t] = g_sar[o];
    }
    __syncthreads();

    int w = threadIdx.x >> 5, lane = threadIdx.x & 31;
    for (int i = s + NSPLIT * w; i < M; i += NSPLIT * 8) {
        float ix1 = sx1[i], iy1 = sy1[i], ix2 = sx2[i], iy2 = sy2[i], ia = sar[i];
        int jw0 = i >> 5;
        for (int jw = jw0; jw < 32; jw++) {
            int j = (jw << 5) + lane;
            bool p = false;
            if (j > i && j < M) {
                float iw = fmaxf(__fsub_rn(fminf(ix2, sx2[j]), fmaxf(ix1, sx1[j])), 0.0f);
                float ih = fmaxf(__fsub_rn(fminf(iy2, sy2[j]), fmaxf(iy1, sy1[j])), 0.0f);
                float inter = __fmul_rn(iw, ih);
                float denom = __fsub_rn(__fadd_rn(ia, sar[j]), inter);
                p = __fdiv_rn(inter, denom) > 0.5f;
            }
            u32 m = __ballot_sync(0xffffffffu, p);
            if (lane == 0) g_mask[((size_t)(bc * KP + i) << 5) + jw] = m;
        }
    }
}

// ---------------------------------------------------------------------------
// Serial greedy scan (one warp per (b,c)) with diagonal-word trick + 16-deep
// prefetch, then compaction of kept entries into sorted key lists.
__global__ void k2c_scan() {
    int bc   = blockIdx.x;
    int lane = threadIdx.x;
    int c    = bc & 7;
    int M    = g_M[bc];

    const u32* mrow = g_mask + ((size_t)(bc * KP) << 5);

    u32 RW[16], DG[16];
#pragma unroll
    for (int d = 0; d < 16; d++) {
        RW[d] = (d < M) ? mrow[(d << 5) + lane]      : 0u;
        DG[d] = (d < M) ? mrow[(d << 5) + (d >> 5)]  : 0u;
    }

    u32 remv = 0u;
    u32 keepreg = 0u;
    int nG = (M + 31) >> 5;

    for (int g = 0; g < nG; g++) {
        u32 cur = __shfl_sync(0xffffffffu, remv, g);
        u32 valid = (lane >= g) ? 0xffffffffu : 0u;
        u32 kw = 0u;
#pragma unroll
        for (int sub = 0; sub < 2; sub++) {
#pragma unroll
            for (int d = 0; d < 16; d++) {
                int i = (g << 5) + (sub << 4) + d;
                u32 rw = RW[d], dg = DG[d];
                int ip = i + 16;
                RW[d] = (ip < M) ? mrow[(ip << 5) + lane]     : 0u;
                DG[d] = (ip < M) ? mrow[(ip << 5) + (ip >> 5)] : 0u;
                if (i < M && !((cur >> (i & 31)) & 1u)) {
                    kw |= 1u << (i & 31);
                    cur |= dg;
                    remv |= rw & valid;
                }
            }
        }
        if (lane == g) keepreg = kw;
    }

    // compact kept entries (order preserved -> still score-sorted)
    int cntl = __popc(keepreg);
    int pre = cntl;
#pragma unroll
    for (int o = 1; o < 32; o <<= 1) {
        int vv = __shfl_up_sync(0xffffffffu, pre, o);
        if (lane >= o) pre += vv;
    }
    int excl = pre - cntl;
    int total = __shfl_sync(0xffffffffu, pre, 31);
    if (lane == 0) g_kcnt[bc] = total;

    u32 wbits = keepreg;
    int off = excl;
    while (wbits) {
        int b2 = __ffs(wbits) - 1;
        wbits &= wbits - 1;
        int i = (lane << 5) + b2;
        u64 sk = g_skey[bc * KP + i];
        u32 t = (u32)(c * KP + i);
        g_ckey[bc * KP + off] = (sk & 0xffffffff00000000ull) | (u64)(~t);
        off++;
    }
}

// ---------------------------------------------------------------------------
// Final top-100 per batch: sort top-128 kept per class (8*128 = 1024 keys).
__global__ void k3_topk(const float* __restrict__ boxes,
                        const float* __restrict__ rot,
                        const float* __restrict__ trans,
                        float* __restrict__ out) {
    __shared__ u64 keys[1024];
    int b = blockIdx.x, tid = threadIdx.x;
    int c = tid >> 7, k = tid & 127;
    int bc = b * 8 + c;
    u64 key = 0ull;
    if (k < g_kcnt[bc]) key = g_ckey[bc * KP + k];
    keys[tid] = key;
    __syncthreads();
    bitonic_desc(keys, 1024, tid, 1024);

    if (tid < MAXD) {
        float* ob   = out;
        float* os   = out + 3200;
        float* ol   = out + 4000;
        float* orot = out + 4800;
        float* otr  = out + 7200;
        int base = b * MAXD + tid;

        u64 kk = keys[tid];
        if (kk != 0ull) {
            u32 t = ~(u32)kk;
            int c2   = (int)(t >> 10);
            int slot = (int)(t & 1023u);
            int idx  = g_sidx[(b * 8 + c2) * KP + slot];
            float s  = __uint_as_float((u32)(kk >> 32));
            size_t g = (size_t)(b * NN + idx);
            float4 bp = reinterpret_cast<const float4*>(boxes)[g];
            ob[base * 4 + 0] = bp.x;
            ob[base * 4 + 1] = bp.y;
            ob[base * 4 + 2] = bp.z;
            ob[base * 4 + 3] = bp.w;
            os[base] = s;
            ol[base] = (float)c2;
            const float* rp = rot + g * 3;
            orot[base * 3 + 0] = rp[0];
            orot[base * 3 + 1] = rp[1];
            orot[base * 3 + 2] = rp[2];
            const float* tp = trans + g * 3;
            otr[base * 3 + 0] = tp[0];
            otr[base * 3 + 1] = tp[1];
            otr[base * 3 + 2] = tp[2];
        } else {
            ob[base * 4 + 0] = -1.0f;
            ob[base * 4 + 1] = -1.0f;
            ob[base * 4 + 2] = -1.0f;
            ob[base * 4 + 3] = -1.0f;
            os[base] = -1.0f;
            ol[base] = -1.0f;
            orot[base * 3 + 0] = -1.0f;
            orot[base * 3 + 1] = -1.0f;
            orot[base * 3 + 2] = -1.0f;
            otr[base * 3 + 0] = -1.0f;
            otr[base * 3 + 1] = -1.0f;
            otr[base * 3 + 2] = -1.0f;
        }
    }
}

// ---------------------------------------------------------------------------
extern "C" void kernel_launch(void* const* d_in, const int* in_sizes, int n_in,
                              void* d_out, int out_size) {
    const float* boxes = (const float*)d_in[0];
    const float* cls   = (const float*)d_in[1];
    const float* rot   = (const float*)d_in[2];
    const float* trans = (const float*)d_in[3];
    float* out = (float*)d_out;

    k0_init<<<1, 64>>>();
    k1_cand<<<(BB * NN + 255) / 256, 256>>>(cls);
    k2a_sort<<<BB * CC, 1024>>>(boxes);
    k2b_mask<<<BB * CC * NSPLIT, 256>>>();
    k2c_scan<<<BB * CC, 32>>>();
    k3_topk<<<BB, 1024>>>(boxes, rot, trans, out);
}